// round 14
// baseline (speedup 1.0000x reference)
#include <cuda_runtime.h>

// Problem constants
#define BB     16
#define NCTX   1024
#define NG     64          // grid points per axis (NX == NY == 64)
#define MROWS  192         // 64 i-rows * 3 channels
#define KSPL   8           // split-K factor
#define KCH    (NCTX/KSPL) // 128 n per CTA

typedef unsigned long long u64;

// split-K partial results: [b][ks][m=192][j=64]
__device__ float g_partial[BB * KSPL * MROWS * NG];

__device__ __forceinline__ u64 pack2(float lo, float hi) {
    u64 d;
    asm("mov.b64 %0, {%1, %2};" : "=l"(d)
        : "r"(__float_as_uint(lo)), "r"(__float_as_uint(hi)));
    return d;
}
__device__ __forceinline__ void unpack2(u64 v, float& lo, float& hi) {
    unsigned a, b;
    asm("mov.b64 {%0, %1}, %2;" : "=r"(a), "=r"(b) : "l"(v));
    lo = __uint_as_float(a);
    hi = __uint_as_float(b);
}
__device__ __forceinline__ u64 mul2(u64 a, u64 b) {
    u64 d;
    asm("mul.rn.f32x2 %0, %1, %2;" : "=l"(d) : "l"(a), "l"(b));
    return d;
}
__device__ __forceinline__ u64 fma2(u64 a, u64 b, u64 c) {
    u64 d;
    asm("fma.rn.f32x2 %0, %1, %2, %3;" : "=l"(d) : "l"(a), "l"(b), "l"(c));
    return d;
}

// ---------------------------------------------------------------------------
// Kernel A: R6's exact inner-loop structure (unroll 2, pack2-on-the-fly,
// depth-1 prefetch) at 512 threads: per-thread j-tile halved to 4 cols so
// register pressure DROPS (acc 24 regs, prefetch ~10) while warps/SMSP double
// (2 -> 4) to attack the measured latency-bound profile (issue 47% -> ~80%).
//   P[n, j] = exp(-0.5*(xs[j]-Xx)^2/l^2)
//   Q[n, i] = exp(-0.5*(ys[i]-Xy)^2/l^2)
//   C[i*3+c, j] += sum_n Q[n,i] * ey_c[n] * P[n,j]   (ey = {1, y0, y1})
// Thread tile: 6 m-rows (i pair 2r,2r+1 x 3 channels) x 4 j-cols.
// ---------------------------------------------------------------------------
__global__ void __launch_bounds__(512, 1)
equiv_gemm_kernel(const float* __restrict__ X,
                  const float* __restrict__ Y,
                  const float* __restrict__ lls)
{
    extern __shared__ float sm[];
    float* P_sm  = sm;                 // [KCH][64]
    float* Q_sm  = sm + KCH * 64;      // [KCH][64]
    float* ey_sm = sm + 2 * KCH * 64;  // [KCH][2]

    const int ks  = blockIdx.x;
    const int b   = blockIdx.y;
    const int tid = threadIdx.x;
    const int n0  = ks * KCH;

    const float invl2 = __expf(-2.0f * lls[0]);   // 1 / l^2
    const float step  = 20.0f / 63.0f;

    // ---- Phase A: P and Q. Four threads per n-row, 16 j each. ----
    {
        const int nl = tid >> 2;
        const int j0 = (tid & 3) * 16;
        const int n  = b * NCTX + n0 + nl;
        const float xx = X[2 * n];
        const float xy = X[2 * n + 1];
        float* prow = P_sm + nl * 64;
        float* qrow = Q_sm + nl * 64;
        #pragma unroll 8
        for (int j = j0; j < j0 + 16; ++j) {
            const float gx = -10.0f + (float)j * step;   // xs[j]
            const float gy =  10.0f - (float)j * step;   // ys[i]
            const float dx = gx - xx;
            const float dy = gy - xy;
            prow[j] = __expf(-0.5f * dx * dx * invl2);
            qrow[j] = __expf(-0.5f * dy * dy * invl2);
        }
        // ey: 256 contiguous floats (y0,y1 pairs)
        if (tid < 2 * KCH)
            ey_sm[tid] = Y[(b * NCTX + n0) * 2 + tid];
    }
    __syncthreads();

    // ---- Phase B: GEMM with f32x2 packed FMA (R6 structure, 4-col tile) ----
    const int r  = tid & 31;    // m-tile: rows 6r .. 6r+5  (i = 2r, 2r+1)
    const int q  = tid >> 5;    // 16 warps
    const int jb = q * 4;       // j-tile: cols 4q .. 4q+3

    u64 acc[3][4];
    #pragma unroll
    for (int c = 0; c < 3; ++c)
        #pragma unroll
        for (int v = 0; v < 4; ++v)
            acc[c][v] = 0ULL;

    // prefetch k=0
    u64    qq = *(const u64*)&Q_sm[2 * r];
    float2 yv = *(const float2*)&ey_sm[0];
    float4 pa = *(const float4*)&P_sm[jb];

    #pragma unroll 2
    for (int k = 0; k < KCH; ++k) {
        const u64    qq_c = qq;
        const float2 yv_c = yv;
        const float4 pa_c = pa;
        if (k + 1 < KCH) {
            qq = *(const u64*)&Q_sm[(k + 1) * 64 + 2 * r];
            yv = *(const float2*)&ey_sm[2 * (k + 1)];
            pa = *(const float4*)&P_sm[(k + 1) * 64 + jb];
        }

        const u64 yd0 = pack2(yv_c.x, yv_c.x);
        const u64 yd1 = pack2(yv_c.y, yv_c.y);
        const u64 m1  = mul2(qq_c, yd0);   // {q0*y0, q1*y0}
        const u64 m2  = mul2(qq_c, yd1);   // {q0*y1, q1*y1}

        const float pv[4] = {pa_c.x, pa_c.y, pa_c.z, pa_c.w};
        #pragma unroll
        for (int v = 0; v < 4; ++v) {
            const u64 pd = pack2(pv[v], pv[v]);
            acc[0][v] = fma2(qq_c, pd, acc[0][v]);
            acc[1][v] = fma2(m1,   pd, acc[1][v]);
            acc[2][v] = fma2(m2,   pd, acc[2][v]);
        }
    }
    __syncthreads();

    // ---- Epilogue: stage C in smem (reuse P/Q region), coalesced store ----
    float* C_sm = sm;   // 192*64 = 12288 floats <= 16384 available
    #pragma unroll
    for (int c = 0; c < 3; ++c)
        #pragma unroll
        for (int v = 0; v < 4; ++v) {
            float lo, hi;
            unpack2(acc[c][v], lo, hi);
            C_sm[(6 * r + c)     * 64 + jb + v] = lo;   // i = 2r
            C_sm[(6 * r + 3 + c) * 64 + jb + v] = hi;   // i = 2r+1
        }
    __syncthreads();

    float4* dst = (float4*)(g_partial + (size_t)(b * KSPL + ks) * (MROWS * NG));
    const float4* src = (const float4*)C_sm;
    #pragma unroll
    for (int idx = tid; idx < MROWS * NG / 4; idx += 512)
        dst[idx] = src[idx];
}

// ---------------------------------------------------------------------------
// Kernel B: reduce split-K partials (R12's max-parallelism version — best
// measured). One thread per scalar output element: 196608 threads, 8
// independent coalesced loads each; ch 1/2 re-sum ch0 for the density divide.
// ---------------------------------------------------------------------------
__global__ void __launch_bounds__(256)
equiv_reduce_kernel(float* __restrict__ out)
{
    const int t   = blockIdx.x * 256 + threadIdx.x;   // 196608
    const int ch  = t >> 16;                          // 0..2
    const int rem = t & 65535;                        // b*4096 + i*64 + j
    const int b   = rem >> 12;
    const int pos = rem & 4095;                       // i*64 + j
    const int i   = pos >> 6;

    const float* base = g_partial +
        ((size_t)b * KSPL * MROWS + i * 3) * NG + (pos & 63);

    float s = 0.0f;
    #pragma unroll
    for (int sk = 0; sk < KSPL; ++sk)
        s += base[(size_t)sk * MROWS * NG + ch * NG];

    float o = s;
    if (ch != 0) {
        float d = 0.0f;
        #pragma unroll
        for (int sk = 0; sk < KSPL; ++sk)
            d += base[(size_t)sk * MROWS * NG];
        o = s / d;
    }

    out[(b * 3 + ch) * 4096 + pos] = o;
}

// ---------------------------------------------------------------------------
extern "C" void kernel_launch(void* const* d_in, const int* in_sizes, int n_in,
                              void* d_out, int out_size)
{
    const float* X   = (const float*)d_in[0];
    const float* Y   = (const float*)d_in[1];
    const float* lls = (const float*)d_in[2];
    float* out = (float*)d_out;

    const size_t smem_bytes = (size_t)(2 * KCH * 64 + 2 * KCH) * sizeof(float); // 66560
    cudaFuncSetAttribute(equiv_gemm_kernel,
                         cudaFuncAttributeMaxDynamicSharedMemorySize,
                         (int)smem_bytes);

    equiv_gemm_kernel<<<dim3(KSPL, BB), 512, smem_bytes>>>(X, Y, lls);
    equiv_reduce_kernel<<<(3 * BB * NG * NG) / 256, 256>>>(out);
}

// round 16
// speedup vs baseline: 1.2240x; 1.2240x over previous
#include <cuda_runtime.h>

// Problem constants
#define BB     16
#define NCTX   1024
#define NG     64          // grid points per axis (NX == NY == 64)
#define MROWS  192         // 64 i-rows * 3 channels
#define KSPL   8           // split-K factor
#define KCH    (NCTX/KSPL) // 128 n per CTA

typedef unsigned long long u64;

// split-K partial results: [b][ks][m=192][j=64]
__device__ float g_partial[BB * KSPL * MROWS * NG];

__device__ __forceinline__ u64 pack2(float lo, float hi) {
    u64 d;
    asm("mov.b64 %0, {%1, %2};" : "=l"(d)
        : "r"(__float_as_uint(lo)), "r"(__float_as_uint(hi)));
    return d;
}
__device__ __forceinline__ void unpack2(u64 v, float& lo, float& hi) {
    unsigned a, b;
    asm("mov.b64 {%0, %1}, %2;" : "=r"(a), "=r"(b) : "l"(v));
    lo = __uint_as_float(a);
    hi = __uint_as_float(b);
}
__device__ __forceinline__ u64 mul2(u64 a, u64 b) {
    u64 d;
    asm("mul.rn.f32x2 %0, %1, %2;" : "=l"(d) : "l"(a), "l"(b));
    return d;
}
__device__ __forceinline__ u64 fma2(u64 a, u64 b, u64 c) {
    u64 d;
    asm("fma.rn.f32x2 %0, %1, %2, %3;" : "=l"(d) : "l"(a), "l"(b), "l"(c));
    return d;
}

// ---------------------------------------------------------------------------
// Kernel A: VERBATIM the proven R6 GEMM (20.96us total config). Do not touch.
//   P[n, j] = exp(-0.5*(xs[j]-Xx)^2/l^2)
//   Q[n, i] = exp(-0.5*(ys[i]-Xy)^2/l^2)
//   C[i*3+c, j] += sum_n Q[n,i] * ey_c[n] * P[n,j]   (ey = {1, y0, y1})
// Thread tile: 6 m-rows (i pair 2r,2r+1 x 3 channels) x 8 j-cols.
// ---------------------------------------------------------------------------
__global__ void __launch_bounds__(256, 1)
equiv_gemm_kernel(const float* __restrict__ X,
                  const float* __restrict__ Y,
                  const float* __restrict__ lls)
{
    extern __shared__ float sm[];
    float* P_sm  = sm;                 // [KCH][64]
    float* Q_sm  = sm + KCH * 64;      // [KCH][64]
    float* ey_sm = sm + 2 * KCH * 64;  // [KCH][2]

    const int ks  = blockIdx.x;
    const int b   = blockIdx.y;
    const int tid = threadIdx.x;
    const int n0  = ks * KCH;

    const float invl2 = __expf(-2.0f * lls[0]);   // 1 / l^2
    const float step  = 20.0f / 63.0f;

    // ---- Phase A: P and Q. Two threads per n-row, 32 j each. ----
    {
        const int nl = tid >> 1;
        const int j0 = (tid & 1) * 32;
        const int n  = b * NCTX + n0 + nl;
        const float xx = X[2 * n];
        const float xy = X[2 * n + 1];
        float* prow = P_sm + nl * 64;
        float* qrow = Q_sm + nl * 64;
        #pragma unroll 8
        for (int j = j0; j < j0 + 32; ++j) {
            const float gx = -10.0f + (float)j * step;   // xs[j]
            const float gy =  10.0f - (float)j * step;   // ys[i]
            const float dx = gx - xx;
            const float dy = gy - xy;
            prow[j] = __expf(-0.5f * dx * dx * invl2);
            qrow[j] = __expf(-0.5f * dy * dy * invl2);
        }
        // ey: 256 contiguous floats (y0,y1 pairs)
        ey_sm[tid] = Y[(b * NCTX + n0) * 2 + tid];
    }
    __syncthreads();

    // ---- Phase B: GEMM with f32x2 packed FMA ----
    const int r  = tid & 31;    // m-tile: rows 6r .. 6r+5  (i = 2r, 2r+1)
    const int q  = tid >> 5;    // j-tile: cols 8q .. 8q+7
    const int jb = q * 8;

    u64 acc[3][8];
    #pragma unroll
    for (int c = 0; c < 3; ++c)
        #pragma unroll
        for (int v = 0; v < 8; ++v)
            acc[c][v] = 0ULL;

    // prefetch k=0
    u64    qq = *(const u64*)&Q_sm[2 * r];
    float2 yv = *(const float2*)&ey_sm[0];
    float4 pa = *(const float4*)&P_sm[jb];
    float4 pb = *(const float4*)&P_sm[jb + 4];

    #pragma unroll 2
    for (int k = 0; k < KCH; ++k) {
        const u64    qq_c = qq;
        const float2 yv_c = yv;
        const float4 pa_c = pa;
        const float4 pb_c = pb;
        if (k + 1 < KCH) {
            qq = *(const u64*)&Q_sm[(k + 1) * 64 + 2 * r];
            yv = *(const float2*)&ey_sm[2 * (k + 1)];
            pa = *(const float4*)&P_sm[(k + 1) * 64 + jb];
            pb = *(const float4*)&P_sm[(k + 1) * 64 + jb + 4];
        }

        const u64 yd0 = pack2(yv_c.x, yv_c.x);
        const u64 yd1 = pack2(yv_c.y, yv_c.y);
        const u64 m1  = mul2(qq_c, yd0);   // {q0*y0, q1*y0}
        const u64 m2  = mul2(qq_c, yd1);   // {q0*y1, q1*y1}

        const float pv[8] = {pa_c.x, pa_c.y, pa_c.z, pa_c.w,
                             pb_c.x, pb_c.y, pb_c.z, pb_c.w};
        #pragma unroll
        for (int v = 0; v < 8; ++v) {
            const u64 pd = pack2(pv[v], pv[v]);
            acc[0][v] = fma2(qq_c, pd, acc[0][v]);
            acc[1][v] = fma2(m1,   pd, acc[1][v]);
            acc[2][v] = fma2(m2,   pd, acc[2][v]);
        }
    }
    __syncthreads();

    // ---- Epilogue: stage C in smem (reuse P/Q region), coalesced store ----
    float* C_sm = sm;   // 192*64 = 12288 floats <= 16384 available
    #pragma unroll
    for (int c = 0; c < 3; ++c)
        #pragma unroll
        for (int v = 0; v < 8; ++v) {
            float lo, hi;
            unpack2(acc[c][v], lo, hi);
            C_sm[(6 * r + c)     * 64 + jb + v] = lo;   // i = 2r
            C_sm[(6 * r + 3 + c) * 64 + jb + v] = hi;   // i = 2r+1
        }
    __syncthreads();

    float4* dst = (float4*)(g_partial + (size_t)(b * KSPL + ks) * (MROWS * NG));
    const float4* src = (const float4*)C_sm;
    #pragma unroll
    for (int idx = tid; idx < MROWS * NG / 4; idx += 256)
        dst[idx] = src[idx];
}

// ---------------------------------------------------------------------------
// Kernel B: VERBATIM the R6 reduce (float4, 16384 threads), plus PDL:
// the grid launches early (overlapping kernel A's tail) and blocks on
// cudaGridDependencySynchronize() before touching the partials.
// ---------------------------------------------------------------------------
__global__ void __launch_bounds__(128)
equiv_reduce_kernel(float* __restrict__ out)
{
    const int t   = blockIdx.x * 128 + threadIdx.x;   // 16384: (b, i, j/4)
    const int b   = t >> 10;
    const int rem = t & 1023;
    const int i   = rem >> 4;
    const int j4  = (rem & 15) * 4;

    const float* p0 = g_partial + ((size_t)(b * KSPL) * MROWS + i * 3) * NG + j4;

    // Wait for kernel A's partials (PDL ordering point).
    cudaGridDependencySynchronize();

    float4 s0 = make_float4(0.f, 0.f, 0.f, 0.f);
    float4 s1 = s0, s2 = s0;
    #pragma unroll
    for (int s = 0; s < KSPL; ++s) {
        const float* p = p0 + (size_t)s * MROWS * NG;
        const float4 v0 = *(const float4*)(p);
        const float4 v1 = *(const float4*)(p + NG);
        const float4 v2 = *(const float4*)(p + 2 * NG);
        s0.x += v0.x; s0.y += v0.y; s0.z += v0.z; s0.w += v0.w;
        s1.x += v1.x; s1.y += v1.y; s1.z += v1.z; s1.w += v1.w;
        s2.x += v2.x; s2.y += v2.y; s2.z += v2.z; s2.w += v2.w;
    }

    const int base = i * 64 + j4;
    float4 o1 = make_float4(s1.x / s0.x, s1.y / s0.y, s1.z / s0.z, s1.w / s0.w);
    float4 o2 = make_float4(s2.x / s0.x, s2.y / s0.y, s2.z / s0.z, s2.w / s0.w);
    *(float4*)&out[(b * 3 + 0) * 4096 + base] = s0;
    *(float4*)&out[(b * 3 + 1) * 4096 + base] = o1;
    *(float4*)&out[(b * 3 + 2) * 4096 + base] = o2;
}

// ---------------------------------------------------------------------------
extern "C" void kernel_launch(void* const* d_in, const int* in_sizes, int n_in,
                              void* d_out, int out_size)
{
    const float* X   = (const float*)d_in[0];
    const float* Y   = (const float*)d_in[1];
    const float* lls = (const float*)d_in[2];
    float* out = (float*)d_out;

    const size_t smem_bytes = (size_t)(2 * KCH * 64 + 2 * KCH) * sizeof(float); // 66560
    cudaFuncSetAttribute(equiv_gemm_kernel,
                         cudaFuncAttributeMaxDynamicSharedMemorySize,
                         (int)smem_bytes);

    equiv_gemm_kernel<<<dim3(KSPL, BB), 256, smem_bytes>>>(X, Y, lls);

    // Reduce with programmatic dependent launch: grid spins up while the GEMM
    // drains; cudaGridDependencySynchronize() inside enforces data ordering.
    cudaLaunchConfig_t cfg = {};
    cfg.gridDim  = dim3((BB * NG * NG / 4) / 128);
    cfg.blockDim = dim3(128);
    cfg.dynamicSmemBytes = 0;
    cfg.stream = 0;
    cudaLaunchAttribute attrs[1];
    attrs[0].id = cudaLaunchAttributeProgrammaticStreamSerialization;
    attrs[0].val.programmaticStreamSerializationAllowed = 1;
    cfg.attrs = attrs;
    cfg.numAttrs = 1;
    cudaLaunchKernelEx(&cfg, equiv_reduce_kernel, out);
}